// round 7
// baseline (speedup 1.0000x reference)
#include <cuda_runtime.h>
#include <cuda_bf16.h>

// RGBToHVI: elementwise, planar (16, 3, 1024, 1024) fp32. HBM-bound (~402 MB).
// V2: 2x float4 per thread (6 front-batched LDG.128 -> 2x MLP), branchless
// hue cascade (FSEL instead of BSSY/BSYNC), streaming cache hints.

#define PLANE4   262144            // (1024*1024)/4 float4 per channel plane
#define NPIX4    4194304           // 16 * PLANE4
#define EPS_F    1e-8f
#define PI_F     3.14159265358979f

__device__ __forceinline__ void hvi_pixel(float r, float g, float b, float k,
                                          float& X, float& Y, float& Z)
{
    const float v  = fmaxf(r, fmaxf(g, b));
    const float mn = fminf(r, fminf(g, b));
    const float chroma = v - mn;
    const float rd = __frcp_rn(chroma + EPS_F);

    // Branchless jnp.where cascade (later where wins -> apply in forward order):
    float hr = (g - b) * rd;                      // in [-1, 1]
    hr = (hr < 0.0f) ? hr + 6.0f : hr;            // x % 6.0 (positive divisor)
    const float hg = 2.0f + (b - r) * rd;
    const float hb = 4.0f + (r - g) * rd;

    float hue = (b == v)  ? hb   : 0.0f;
    hue       = (g == v)  ? hg   : hue;
    hue       = (r == v)  ? hr   : hue;
    hue       = (mn == v) ? 0.0f : hue;
    hue *= (1.0f / 6.0f);

    const float sat = (v == 0.0f) ? 0.0f : chroma * __frcp_rn(v + EPS_F);

    // color_sensitive = (sin(v*pi/2) + eps)^k, v in [0,1] so base >= eps > 0
    const float s  = __sinf(v * (0.5f * PI_F)) + EPS_F;
    const float cs = __powf(s, k);                // EX2(k * LG2(s))

    const float ang = (2.0f * PI_F) * hue;
    const float m = cs * sat;
    X = m * __cosf(ang);
    Y = m * __sinf(ang);
    Z = v;
}

__global__ __launch_bounds__(256)
void rgb_to_hvi_kernel(const float4* __restrict__ img,
                       const float*  __restrict__ dk,
                       float4* __restrict__ out)
{
    // Each thread: 2 float4 groups, 256 apart (both warp-coalesced).
    const int i0 = blockIdx.x * (2 * 256) + threadIdx.x;
    const int i1 = i0 + 256;

    const float k = __ldg(dk);

    const int  b0 = i0 >> 18;                     // batch index
    const long base0 = (long)b0 * (3 * PLANE4) + (i0 & (PLANE4 - 1));
    const int  b1 = i1 >> 18;
    const long base1 = (long)b1 * (3 * PLANE4) + (i1 & (PLANE4 - 1));

    // 6 front-batched 128-bit streaming loads
    const float4 r0 = __ldcs(&img[base0]);
    const float4 g0 = __ldcs(&img[base0 + PLANE4]);
    const float4 bb0 = __ldcs(&img[base0 + 2 * PLANE4]);
    const float4 r1 = __ldcs(&img[base1]);
    const float4 g1 = __ldcs(&img[base1 + PLANE4]);
    const float4 bb1 = __ldcs(&img[base1 + 2 * PLANE4]);

    float4 X0, Y0, Z0, X1, Y1, Z1;

    hvi_pixel(r0.x, g0.x, bb0.x, k, X0.x, Y0.x, Z0.x);
    hvi_pixel(r0.y, g0.y, bb0.y, k, X0.y, Y0.y, Z0.y);
    hvi_pixel(r0.z, g0.z, bb0.z, k, X0.z, Y0.z, Z0.z);
    hvi_pixel(r0.w, g0.w, bb0.w, k, X0.w, Y0.w, Z0.w);

    hvi_pixel(r1.x, g1.x, bb1.x, k, X1.x, Y1.x, Z1.x);
    hvi_pixel(r1.y, g1.y, bb1.y, k, X1.y, Y1.y, Z1.y);
    hvi_pixel(r1.z, g1.z, bb1.z, k, X1.z, Y1.z, Z1.z);
    hvi_pixel(r1.w, g1.w, bb1.w, k, X1.w, Y1.w, Z1.w);

    __stcs(&out[base0],              X0);
    __stcs(&out[base0 + PLANE4],     Y0);
    __stcs(&out[base0 + 2 * PLANE4], Z0);
    __stcs(&out[base1],              X1);
    __stcs(&out[base1 + PLANE4],     Y1);
    __stcs(&out[base1 + 2 * PLANE4], Z1);
}

extern "C" void kernel_launch(void* const* d_in, const int* in_sizes, int n_in,
                              void* d_out, int out_size)
{
    const float4* img = (const float4*)d_in[0];
    const float*  dk  = (const float*)d_in[1];
    float4* out = (float4*)d_out;

    const int threads = 256;
    const int blocks  = NPIX4 / (2 * threads);    // 8192 (NPIX4 = 2^22, exact)
    rgb_to_hvi_kernel<<<blocks, threads>>>(img, dk, out);
}

// round 8
// speedup vs baseline: 1.0320x; 1.0320x over previous
#include <cuda_runtime.h>
#include <cuda_bf16.h>

// RGBToHVI: elementwise, planar (16, 3, 1024, 1024) fp32. HBM-bound (~402 MB).
// V3: back to 1 float4-triple per thread (32 regs, high occupancy — V2's 2x
// unroll cost occ 86%->53% and regressed). Branchless hue cascade + streaming
// cache hints, launch_bounds(256,8) to pin occupancy.

#define PLANE4   262144            // (1024*1024)/4 float4 per channel plane
#define NPIX4    4194304           // 16 * PLANE4
#define EPS_F    1e-8f
#define PI_F     3.14159265358979f

__device__ __forceinline__ void hvi_pixel(float r, float g, float b, float k,
                                          float& X, float& Y, float& Z)
{
    const float v  = fmaxf(r, fmaxf(g, b));
    const float mn = fminf(r, fminf(g, b));
    const float chroma = v - mn;
    const float rd = __frcp_rn(chroma + EPS_F);

    // Branchless jnp.where cascade (later where wins):
    //   priority: mn==v -> 0, r==v -> mod6 arm, g==v, b==v, else 0
    float hr = (g - b) * rd;                      // in [-1, 1]
    hr = (hr < 0.0f) ? hr + 6.0f : hr;            // x % 6.0 (positive divisor)
    const float hg = 2.0f + (b - r) * rd;
    const float hb = 4.0f + (r - g) * rd;

    float hue = (b == v)  ? hb   : 0.0f;
    hue       = (g == v)  ? hg   : hue;
    hue       = (r == v)  ? hr   : hue;
    hue       = (mn == v) ? 0.0f : hue;
    hue *= (1.0f / 6.0f);

    const float sat = (v == 0.0f) ? 0.0f : chroma * __frcp_rn(v + EPS_F);

    // color_sensitive = (sin(v*pi/2) + eps)^k, v in [0,1] so base >= eps > 0
    const float s  = __sinf(v * (0.5f * PI_F)) + EPS_F;
    const float cs = __powf(s, k);                // EX2(k * LG2(s))

    const float ang = (2.0f * PI_F) * hue;
    const float m = cs * sat;
    X = m * __cosf(ang);
    Y = m * __sinf(ang);
    Z = v;
}

__global__ __launch_bounds__(256, 8)
void rgb_to_hvi_kernel(const float4* __restrict__ img,
                       const float*  __restrict__ dk,
                       float4* __restrict__ out)
{
    const int i = blockIdx.x * blockDim.x + threadIdx.x;

    const float k = __ldg(dk);

    const int batch = i >> 18;                    // / PLANE4
    const int w     = i & (PLANE4 - 1);
    const long base = (long)batch * (3 * PLANE4) + w;

    // Three front-batched 128-bit streaming loads
    const float4 rv = __ldcs(&img[base]);
    const float4 gv = __ldcs(&img[base + PLANE4]);
    const float4 bv = __ldcs(&img[base + 2 * PLANE4]);

    float4 Xv, Yv, Zv;
    hvi_pixel(rv.x, gv.x, bv.x, k, Xv.x, Yv.x, Zv.x);
    hvi_pixel(rv.y, gv.y, bv.y, k, Xv.y, Yv.y, Zv.y);
    hvi_pixel(rv.z, gv.z, bv.z, k, Xv.z, Yv.z, Zv.z);
    hvi_pixel(rv.w, gv.w, bv.w, k, Xv.w, Yv.w, Zv.w);

    __stcs(&out[base],              Xv);
    __stcs(&out[base + PLANE4],     Yv);
    __stcs(&out[base + 2 * PLANE4], Zv);
}

extern "C" void kernel_launch(void* const* d_in, const int* in_sizes, int n_in,
                              void* d_out, int out_size)
{
    const float4* img = (const float4*)d_in[0];
    const float*  dk  = (const float*)d_in[1];
    float4* out = (float4*)d_out;

    const int threads = 256;
    const int blocks  = NPIX4 / threads;          // 16384 (exact)
    rgb_to_hvi_kernel<<<blocks, threads>>>(img, dk, out);
}